// round 5
// baseline (speedup 1.0000x reference)
#include <cuda_runtime.h>
#include <math.h>

#define B_   2
#define N_   6
#define C_   80
#define FH_  16
#define FW_  44
#define D_   112
#define NX_  128
#define NY_  128
#define BN_  (B_*N_)
#define PIX_ (FH_*FW_)          // 704
#define NPIX_ (BN_*PIX_)        // 8448
#define CELLS_ (NX_*NY_)        // 16384
#define OUTN_ (B_*C_*CELLS_)    // 2621440
#define MAXPER_ 1024

__device__ float g_comb[BN_][16];    // bda @ s2e @ inv(intrin)
__device__ float g_idainv[BN_][16];  // inv(ida)
__device__ int   g_cnt[B_*CELLS_];                                   // per-cell entry counts
__device__ unsigned long long g_entries[(size_t)B_*CELLS_*MAXPER_];  // (pix<<32 | weight bits)
__device__ __align__(16) float g_ctxT[(size_t)NPIX_*C_];             // channel-last ctx

// ---------------------------------------------------------------------------
// general 4x4 inverse (adjugate, double precision)
// ---------------------------------------------------------------------------
__device__ void inv4x4d(const float* src, double* out) {
    double m[16];
    #pragma unroll
    for (int i = 0; i < 16; i++) m[i] = (double)src[i];
    double inv[16];
    inv[0]  =  m[5]*m[10]*m[15] - m[5]*m[11]*m[14] - m[9]*m[6]*m[15] + m[9]*m[7]*m[14] + m[13]*m[6]*m[11] - m[13]*m[7]*m[10];
    inv[4]  = -m[4]*m[10]*m[15] + m[4]*m[11]*m[14] + m[8]*m[6]*m[15] - m[8]*m[7]*m[14] - m[12]*m[6]*m[11] + m[12]*m[7]*m[10];
    inv[8]  =  m[4]*m[9]*m[15]  - m[4]*m[11]*m[13] - m[8]*m[5]*m[15] + m[8]*m[7]*m[13] + m[12]*m[5]*m[11] - m[12]*m[7]*m[9];
    inv[12] = -m[4]*m[9]*m[14]  + m[4]*m[10]*m[13] + m[8]*m[5]*m[14] - m[8]*m[6]*m[13] - m[12]*m[5]*m[10] + m[12]*m[6]*m[9];
    inv[1]  = -m[1]*m[10]*m[15] + m[1]*m[11]*m[14] + m[9]*m[2]*m[15] - m[9]*m[3]*m[14] - m[13]*m[2]*m[11] + m[13]*m[3]*m[10];
    inv[5]  =  m[0]*m[10]*m[15] - m[0]*m[11]*m[14] - m[8]*m[2]*m[15] + m[8]*m[3]*m[14] + m[12]*m[2]*m[11] - m[12]*m[3]*m[10];
    inv[9]  = -m[0]*m[9]*m[15]  + m[0]*m[11]*m[13] + m[8]*m[1]*m[15] - m[8]*m[3]*m[13] - m[12]*m[1]*m[11] + m[12]*m[3]*m[9];
    inv[13] =  m[0]*m[9]*m[14]  - m[0]*m[10]*m[13] - m[8]*m[1]*m[14] + m[8]*m[2]*m[13] + m[12]*m[1]*m[10] - m[12]*m[2]*m[9];
    inv[2]  =  m[1]*m[6]*m[15]  - m[1]*m[7]*m[14]  - m[5]*m[2]*m[15] + m[5]*m[3]*m[14] + m[13]*m[2]*m[7]  - m[13]*m[3]*m[6];
    inv[6]  = -m[0]*m[6]*m[15]  + m[0]*m[7]*m[14]  + m[4]*m[2]*m[15] - m[4]*m[3]*m[14] - m[12]*m[2]*m[7]  + m[12]*m[3]*m[6];
    inv[10] =  m[0]*m[5]*m[15]  - m[0]*m[7]*m[13]  - m[4]*m[1]*m[15] + m[4]*m[3]*m[13] + m[12]*m[1]*m[7]  - m[12]*m[3]*m[5];
    inv[14] = -m[0]*m[5]*m[14]  + m[0]*m[6]*m[13]  + m[4]*m[1]*m[14] - m[4]*m[2]*m[13] - m[12]*m[1]*m[6]  + m[12]*m[2]*m[5];
    inv[3]  = -m[1]*m[6]*m[11]  + m[1]*m[7]*m[10]  + m[5]*m[2]*m[11] - m[5]*m[3]*m[10] - m[9]*m[2]*m[7]   + m[9]*m[3]*m[6];
    inv[7]  =  m[0]*m[6]*m[11]  - m[0]*m[7]*m[10]  - m[4]*m[2]*m[11] + m[4]*m[3]*m[10] + m[8]*m[2]*m[7]   - m[8]*m[3]*m[6];
    inv[11] = -m[0]*m[5]*m[11]  + m[0]*m[7]*m[9]   + m[4]*m[1]*m[11] - m[4]*m[3]*m[9]  - m[8]*m[1]*m[7]   + m[8]*m[3]*m[5];
    inv[15] =  m[0]*m[5]*m[10]  - m[0]*m[6]*m[9]   - m[4]*m[1]*m[10] + m[4]*m[2]*m[9]  + m[8]*m[1]*m[6]   - m[8]*m[2]*m[5];
    double det = m[0]*inv[0] + m[1]*inv[4] + m[2]*inv[8] + m[3]*inv[12];
    det = 1.0 / det;
    #pragma unroll
    for (int i = 0; i < 16; i++) out[i] = inv[i] * det;
}

__device__ void mm4d(const double* A, const double* Bm, double* Cm) {
    #pragma unroll
    for (int i = 0; i < 4; i++)
        #pragma unroll
        for (int j = 0; j < 4; j++) {
            double s = 0.0;
            #pragma unroll
            for (int k = 0; k < 4; k++) s += A[i*4+k] * Bm[k*4+j];
            Cm[i*4+j] = s;
        }
}

// ---------------------------------------------------------------------------
__global__ void prep_kernel(const float* __restrict__ s2e,
                            const float* __restrict__ intrin,
                            const float* __restrict__ ida,
                            const float* __restrict__ bda) {
    int i = threadIdx.x;
    if (i >= BN_) return;
    int b = i / N_;
    double Mi[16], Ii[16], S[16], Bd[16], T[16], Cm[16];
    inv4x4d(intrin + i*16, Mi);
    inv4x4d(ida + i*16, Ii);
    #pragma unroll
    for (int k = 0; k < 16; k++) { S[k] = (double)s2e[i*16 + k]; Bd[k] = (double)bda[b*16 + k]; }
    mm4d(S, Mi, T);
    mm4d(Bd, T, Cm);
    #pragma unroll
    for (int k = 0; k < 16; k++) { g_comb[i][k] = (float)Cm[k]; g_idainv[i][k] = (float)Ii[k]; }
}

__global__ __launch_bounds__(256) void zero_cnt_kernel() {
    int i = blockIdx.x * blockDim.x + threadIdx.x;
    if (i < B_*CELLS_) g_cnt[i] = 0;
}

// ---------------------------------------------------------------------------
// build: one CTA (128 threads) per feature-map pixel (b, n, h, w)
//   softmax over D -> geometry/voxel -> run-merge -> emit (pix, weight) entries
//   also writes this pixel's ctx row channel-last into g_ctxT
// ---------------------------------------------------------------------------
__global__ __launch_bounds__(128) void build_kernel(const float* __restrict__ ctx,
                                                    const float* __restrict__ dl) {
    int pix = blockIdx.x;               // bn*704 + h*44 + w
    int bn  = pix / PIX_;
    int hw  = pix - bn * PIX_;
    int h   = hw / FW_;
    int w   = hw - h * FW_;
    int b   = bn / N_;
    int tid = threadIdx.x;

    __shared__ float sctx[C_];
    __shared__ float sw[D_];
    __shared__ int   slin[D_];
    __shared__ float red_[128];
    __shared__ int   s_rlin[D_];
    __shared__ float s_rw[D_];
    __shared__ int   s_nr;

    if (tid < C_) sctx[tid] = ctx[(bn * C_ + tid) * PIX_ + hw];

    // ---- softmax over D=112 ----
    float l = -1e30f;
    if (tid < D_) l = dl[(bn * D_ + tid) * PIX_ + hw];
    red_[tid] = l;
    __syncthreads();
    #pragma unroll
    for (int s = 64; s > 0; s >>= 1) {
        if (tid < s) red_[tid] = fmaxf(red_[tid], red_[tid + s]);
        __syncthreads();
    }
    float mx = red_[0];
    __syncthreads();
    float e = (tid < D_) ? expf(l - mx) : 0.0f;
    red_[tid] = e;
    __syncthreads();
    #pragma unroll
    for (int s = 64; s > 0; s >>= 1) {
        if (tid < s) red_[tid] += red_[tid + s];
        __syncthreads();
    }
    float ssum = red_[0];

    // ctx row -> channel-last global (coalesced float4); sctx is ready after
    // the first __syncthreads above
    if (tid < C_/4) {
        float4 v = make_float4(sctx[tid*4+0], sctx[tid*4+1], sctx[tid*4+2], sctx[tid*4+3]);
        ((float4*)(g_ctxT + (size_t)pix * C_))[tid] = v;
    }

    // ---- geometry & voxel index, one depth bin per thread ----
    if (tid < D_) {
        sw[tid] = e / ssum;
        float dd = 2.25f + 0.5f * (float)tid;            // exact
        float u  = (703.0f / 43.0f) * (float)w;          // linspace(0,703,44)
        float v  = (float)(17 * h);                      // linspace(0,255,16), exact
        const float* Ii = g_idainv[bn];
        float p0 = Ii[0]*u  + Ii[1]*v  + Ii[2]*dd  + Ii[3];
        float p1 = Ii[4]*u  + Ii[5]*v  + Ii[6]*dd  + Ii[7];
        float p2 = Ii[8]*u  + Ii[9]*v  + Ii[10]*dd + Ii[11];
        float p3 = Ii[12]*u + Ii[13]*v + Ii[14]*dd + Ii[15];
        float q0 = p0 * p2, q1 = p1 * p2, q2 = p2, q3 = p3;
        const float* Cm = g_comb[bn];
        float gx = Cm[0]*q0 + Cm[1]*q1 + Cm[2]*q2  + Cm[3]*q3;
        float gy = Cm[4]*q0 + Cm[5]*q1 + Cm[6]*q2  + Cm[7]*q3;
        float gz = Cm[8]*q0 + Cm[9]*q1 + Cm[10]*q2 + Cm[11]*q3;
        const float LO01 = -50.8f - 0.4f;   // vcoord - vsize/2 (f32, matches ref)
        const float LO2  = -1.0f  - 4.0f;
        int ix = (int)floorf(__fdiv_rn(gx - LO01, 0.8f));
        int iy = (int)floorf(__fdiv_rn(gy - LO01, 0.8f));
        int iz = (int)floorf(__fdiv_rn(gz - LO2,  8.0f));
        bool valid = (ix >= 0) && (ix < NX_) && (iy >= 0) && (iy < NY_) && (iz == 0);
        slin[tid] = valid ? (iy * NX_ + ix) : -1;
    }
    __syncthreads();

    // ---- run-length merge of consecutive depths in the same voxel ----
    if (tid == 0) {
        int nr = 0, prev = -1;
        for (int d = 0; d < D_; d++) {
            int li = slin[d];
            if (li < 0) { prev = -1; continue; }
            if (li == prev) {
                s_rw[nr - 1] += sw[d];
            } else {
                s_rlin[nr] = li; s_rw[nr] = sw[d]; nr++; prev = li;
            }
        }
        s_nr = nr;
    }
    __syncthreads();

    // ---- emit entries: one per run (all runs of a pixel hit distinct cells) ----
    int nr = s_nr;
    if (tid < nr) {
        int cell = s_rlin[tid];
        int bidx = b * CELLS_ + cell;
        int slot = atomicAdd(&g_cnt[bidx], 1);
        if (slot < MAXPER_) {
            unsigned long long ent = ((unsigned long long)(unsigned)pix << 32)
                                   | (unsigned long long)__float_as_uint(s_rw[tid]);
            g_entries[(size_t)bidx * MAXPER_ + slot] = ent;
        }
    }
}

// ---------------------------------------------------------------------------
// gather: one CTA (128 threads = 4 warps) per (b, cell).
//   warp w strides entries w, w+4, ...; lanes 0..19 each own one float4 quad
//   of channels. Accumulate in registers, reduce across warps in smem,
//   write each output element exactly once.
// ---------------------------------------------------------------------------
__global__ __launch_bounds__(128) void gather_kernel(float* __restrict__ out) {
    int bidx = blockIdx.x;              // b*CELLS + cell
    int b    = bidx >> 14;
    int cell = bidx & (CELLS_ - 1);
    int tid  = threadIdx.x;
    int wrp  = tid >> 5;
    int lane = tid & 31;

    int cnt = g_cnt[bidx];
    if (cnt > MAXPER_) cnt = MAXPER_;

    const unsigned long long* ebase = g_entries + (size_t)bidx * MAXPER_;
    float ax = 0.f, ay = 0.f, az = 0.f, aw = 0.f;

    for (int e = wrp; e < cnt; e += 4) {
        if (lane < C_/4) {
            unsigned long long ent = ebase[e];   // same addr across lanes -> broadcast
            int   pix = (int)(ent >> 32);
            float wgt = __uint_as_float((unsigned)ent);
            float4 v = ((const float4*)(g_ctxT + (size_t)pix * C_))[lane];
            ax += wgt * v.x; ay += wgt * v.y; az += wgt * v.z; aw += wgt * v.w;
        }
    }

    __shared__ float sacc[4][C_];
    if (lane < C_/4) {
        sacc[wrp][lane*4+0] = ax; sacc[wrp][lane*4+1] = ay;
        sacc[wrp][lane*4+2] = az; sacc[wrp][lane*4+3] = aw;
    }
    __syncthreads();
    if (tid < C_) {
        float s = sacc[0][tid] + sacc[1][tid] + sacc[2][tid] + sacc[3][tid];
        out[((size_t)b * C_ + tid) * CELLS_ + cell] = s;
    }
}

// ---------------------------------------------------------------------------
extern "C" void kernel_launch(void* const* d_in, const int* in_sizes, int n_in,
                              void* d_out, int out_size) {
    const float* ctx    = (const float*)d_in[0];
    const float* dl     = (const float*)d_in[1];
    const float* s2e    = (const float*)d_in[2];
    const float* intrin = (const float*)d_in[3];
    const float* ida    = (const float*)d_in[4];
    const float* bda    = (const float*)d_in[5];
    float* out = (float*)d_out;

    zero_cnt_kernel<<<(B_*CELLS_ + 255) / 256, 256>>>();
    prep_kernel<<<1, 32>>>(s2e, intrin, ida, bda);
    build_kernel<<<NPIX_, 128>>>(ctx, dl);
    gather_kernel<<<B_*CELLS_, 128>>>(out);
}

// round 7
// speedup vs baseline: 1.6101x; 1.6101x over previous
#include <cuda_runtime.h>
#include <math.h>

#define B_   2
#define N_   6
#define C_   80
#define FH_  16
#define FW_  44
#define D_   112
#define NX_  128
#define NY_  128
#define BN_  (B_*N_)
#define PIX_ (FH_*FW_)          // 704
#define NPIX_ (BN_*PIX_)        // 8448
#define CELLS_ (NX_*NY_)        // 16384
#define OUTN_ (B_*C_*CELLS_)    // 2621440

__device__ float g_comb[BN_][16];    // bda @ s2e @ inv(intrin)
__device__ float g_idainv[BN_][16];  // inv(ida)
__device__ __align__(128) float g_scratch[OUTN_];   // [B][Y*X][C] channel-last accumulator

// ---------------------------------------------------------------------------
// general 4x4 inverse (adjugate, double precision)
// ---------------------------------------------------------------------------
__device__ void inv4x4d(const float* src, double* out) {
    double m[16];
    #pragma unroll
    for (int i = 0; i < 16; i++) m[i] = (double)src[i];
    double inv[16];
    inv[0]  =  m[5]*m[10]*m[15] - m[5]*m[11]*m[14] - m[9]*m[6]*m[15] + m[9]*m[7]*m[14] + m[13]*m[6]*m[11] - m[13]*m[7]*m[10];
    inv[4]  = -m[4]*m[10]*m[15] + m[4]*m[11]*m[14] + m[8]*m[6]*m[15] - m[8]*m[7]*m[14] - m[12]*m[6]*m[11] + m[12]*m[7]*m[10];
    inv[8]  =  m[4]*m[9]*m[15]  - m[4]*m[11]*m[13] - m[8]*m[5]*m[15] + m[8]*m[7]*m[13] + m[12]*m[5]*m[11] - m[12]*m[7]*m[9];
    inv[12] = -m[4]*m[9]*m[14]  + m[4]*m[10]*m[13] + m[8]*m[5]*m[14] - m[8]*m[6]*m[13] - m[12]*m[5]*m[10] + m[12]*m[6]*m[9];
    inv[1]  = -m[1]*m[10]*m[15] + m[1]*m[11]*m[14] + m[9]*m[2]*m[15] - m[9]*m[3]*m[14] - m[13]*m[2]*m[11] + m[13]*m[3]*m[10];
    inv[5]  =  m[0]*m[10]*m[15] - m[0]*m[11]*m[14] - m[8]*m[2]*m[15] + m[8]*m[3]*m[14] + m[12]*m[2]*m[11] - m[12]*m[3]*m[10];
    inv[9]  = -m[0]*m[9]*m[15]  + m[0]*m[11]*m[13] + m[8]*m[1]*m[15] - m[8]*m[3]*m[13] - m[12]*m[1]*m[11] + m[12]*m[3]*m[9];
    inv[13] =  m[0]*m[9]*m[14]  - m[0]*m[10]*m[13] - m[8]*m[1]*m[14] + m[8]*m[2]*m[13] + m[12]*m[1]*m[10] - m[12]*m[2]*m[9];
    inv[2]  =  m[1]*m[6]*m[15]  - m[1]*m[7]*m[14]  - m[5]*m[2]*m[15] + m[5]*m[3]*m[14] + m[13]*m[2]*m[7]  - m[13]*m[3]*m[6];
    inv[6]  = -m[0]*m[6]*m[15]  + m[0]*m[7]*m[14]  + m[4]*m[2]*m[15] - m[4]*m[3]*m[14] - m[12]*m[2]*m[7]  + m[12]*m[3]*m[6];
    inv[10] =  m[0]*m[5]*m[15]  - m[0]*m[7]*m[13]  - m[4]*m[1]*m[15] + m[4]*m[3]*m[13] + m[12]*m[1]*m[7]  - m[12]*m[3]*m[5];
    inv[14] = -m[0]*m[5]*m[14]  + m[0]*m[6]*m[13]  + m[4]*m[1]*m[14] - m[4]*m[2]*m[13] - m[12]*m[1]*m[6]  + m[12]*m[2]*m[5];
    inv[3]  = -m[1]*m[6]*m[11]  + m[1]*m[7]*m[10]  + m[5]*m[2]*m[11] - m[5]*m[3]*m[10] - m[9]*m[2]*m[7]   + m[9]*m[3]*m[6];
    inv[7]  =  m[0]*m[6]*m[11]  - m[0]*m[7]*m[10]  - m[4]*m[2]*m[11] + m[4]*m[3]*m[10] + m[8]*m[2]*m[7]   - m[8]*m[3]*m[6];
    inv[11] = -m[0]*m[5]*m[11]  + m[0]*m[7]*m[9]   + m[4]*m[1]*m[11] - m[4]*m[3]*m[9]  - m[8]*m[1]*m[7]   + m[8]*m[3]*m[5];
    inv[15] =  m[0]*m[5]*m[10]  - m[0]*m[6]*m[9]   - m[4]*m[1]*m[10] + m[4]*m[2]*m[9]  + m[8]*m[1]*m[6]   - m[8]*m[2]*m[5];
    double det = m[0]*inv[0] + m[1]*inv[4] + m[2]*inv[8] + m[3]*inv[12];
    det = 1.0 / det;
    #pragma unroll
    for (int i = 0; i < 16; i++) out[i] = inv[i] * det;
}

__device__ void mm4d(const double* A, const double* Bm, double* Cm) {
    #pragma unroll
    for (int i = 0; i < 4; i++)
        #pragma unroll
        for (int j = 0; j < 4; j++) {
            double s = 0.0;
            #pragma unroll
            for (int k = 0; k < 4; k++) s += A[i*4+k] * Bm[k*4+j];
            Cm[i*4+j] = s;
        }
}

// ---------------------------------------------------------------------------
__global__ void prep_kernel(const float* __restrict__ s2e,
                            const float* __restrict__ intrin,
                            const float* __restrict__ ida,
                            const float* __restrict__ bda) {
    int i = threadIdx.x;
    if (i >= BN_) return;
    int b = i / N_;
    double Mi[16], Ii[16], S[16], Bd[16], T[16], Cm[16];
    inv4x4d(intrin + i*16, Mi);
    inv4x4d(ida + i*16, Ii);
    #pragma unroll
    for (int k = 0; k < 16; k++) { S[k] = (double)s2e[i*16 + k]; Bd[k] = (double)bda[b*16 + k]; }
    mm4d(S, Mi, T);
    mm4d(Bd, T, Cm);
    #pragma unroll
    for (int k = 0; k < 16; k++) { g_comb[i][k] = (float)Cm[k]; g_idainv[i][k] = (float)Ii[k]; }
}

__global__ __launch_bounds__(256) void zero_scratch_kernel() {
    int i = blockIdx.x * blockDim.x + threadIdx.x;
    ((float4*)g_scratch)[i] = make_float4(0.f, 0.f, 0.f, 0.f);
}

// ---------------------------------------------------------------------------
// main: one CTA (128 threads = 4 warps) per feature-map pixel.
//   warp-shfl softmax (4 barriers total), parallel head-flag run merge,
//   red.v4 scatter into channel-last scratch.
// ---------------------------------------------------------------------------
__global__ __launch_bounds__(128) void lss_main(const float* __restrict__ ctx,
                                                const float* __restrict__ dl) {
    int pix = blockIdx.x;               // bn*704 + h*44 + w
    int bn  = pix / PIX_;
    int hw  = pix - bn * PIX_;
    int h   = hw / FW_;
    int w   = hw - h * FW_;
    int b   = bn / N_;
    int tid = threadIdx.x;
    int lane = tid & 31, wrp = tid >> 5;

    __shared__ float sctx[C_];
    __shared__ float sw[D_];
    __shared__ int   slin[D_];
    __shared__ float spmax[4];
    __shared__ float spsum[4];
    __shared__ int   s_rlin[D_];
    __shared__ float s_rw[D_];
    __shared__ int   s_nr;

    if (tid == 0) s_nr = 0;
    if (tid < C_) sctx[tid] = ctx[(bn * C_ + tid) * PIX_ + hw];

    // ---- softmax over D=112 (warp shfl + 4-word combine) ----
    float l = (tid < D_) ? dl[(bn * D_ + tid) * PIX_ + hw] : -1e30f;
    float m = l;
    #pragma unroll
    for (int s = 16; s > 0; s >>= 1) m = fmaxf(m, __shfl_xor_sync(0xffffffffu, m, s));
    if (lane == 0) spmax[wrp] = m;
    __syncthreads();
    float mx = fmaxf(fmaxf(spmax[0], spmax[1]), fmaxf(spmax[2], spmax[3]));
    float e = (tid < D_) ? __expf(l - mx) : 0.0f;
    float sum = e;
    #pragma unroll
    for (int s = 16; s > 0; s >>= 1) sum += __shfl_xor_sync(0xffffffffu, sum, s);
    if (lane == 0) spsum[wrp] = sum;
    __syncthreads();
    float rinv = 1.0f / (spsum[0] + spsum[1] + spsum[2] + spsum[3]);

    // ---- geometry & voxel index, one depth bin per thread ----
    if (tid < D_) {
        sw[tid] = e * rinv;
        float dd = 2.25f + 0.5f * (float)tid;            // exact
        float u  = (703.0f / 43.0f) * (float)w;          // linspace(0,703,44)
        float v  = (float)(17 * h);                      // linspace(0,255,16), exact
        const float* Ii = g_idainv[bn];
        float p0 = Ii[0]*u  + Ii[1]*v  + Ii[2]*dd  + Ii[3];
        float p1 = Ii[4]*u  + Ii[5]*v  + Ii[6]*dd  + Ii[7];
        float p2 = Ii[8]*u  + Ii[9]*v  + Ii[10]*dd + Ii[11];
        float p3 = Ii[12]*u + Ii[13]*v + Ii[14]*dd + Ii[15];
        float q0 = p0 * p2, q1 = p1 * p2, q2 = p2, q3 = p3;
        const float* Cm = g_comb[bn];
        float gx = Cm[0]*q0 + Cm[1]*q1 + Cm[2]*q2  + Cm[3]*q3;
        float gy = Cm[4]*q0 + Cm[5]*q1 + Cm[6]*q2  + Cm[7]*q3;
        float gz = Cm[8]*q0 + Cm[9]*q1 + Cm[10]*q2 + Cm[11]*q3;
        const float LO01 = -50.8f - 0.4f;   // vcoord - vsize/2 (f32, matches ref)
        const float LO2  = -1.0f  - 4.0f;
        int ix = (int)floorf(__fdiv_rn(gx - LO01, 0.8f));
        int iy = (int)floorf(__fdiv_rn(gy - LO01, 0.8f));
        int iz = (int)floorf(__fdiv_rn(gz - LO2,  8.0f));
        bool valid = (ix >= 0) && (ix < NX_) && (iy >= 0) && (iy < NY_) && (iz == 0);
        slin[tid] = valid ? (iy * NX_ + ix) : -1;
    }
    __syncthreads();

    // ---- parallel run merge: head threads walk their run (avg 1.6 steps) ----
    if (tid < D_) {
        int li = slin[tid];
        bool head = (li >= 0) && (tid == 0 || slin[tid - 1] != li);
        if (head) {
            float s = sw[tid];
            int k = tid + 1;
            while (k < D_ && slin[k] == li) { s += sw[k]; k++; }
            int slot = atomicAdd(&s_nr, 1);
            s_rlin[slot] = li;
            s_rw[slot]   = s;
        }
    }
    __syncthreads();

    int nr = s_nr;
    if (nr == 0) return;

    // ---- scatter: nr runs x 20 float4 quads into channel-last scratch.
    //      Adjacent threads take consecutive quads of the same run ->
    //      one warp covers a contiguous 320B region (good L2 sector packing).
    float* sbase = g_scratch + (size_t)b * (CELLS_ * C_);
    int total = nr * (C_ / 4);
    int c = tid / nr;
    int r = tid - c * nr;   // NOTE: p-major over runs; recompute per iteration below
    for (int p = tid; p < total; p += 128) {
        int rr = p / (C_ / 4);
        int q4 = p - rr * (C_ / 4);
        float wgt = s_rw[rr];
        float v0 = wgt * sctx[q4*4 + 0];
        float v1 = wgt * sctx[q4*4 + 1];
        float v2 = wgt * sctx[q4*4 + 2];
        float v3 = wgt * sctx[q4*4 + 3];
        float* addr = sbase + (size_t)s_rlin[rr] * C_ + q4 * 4;
        asm volatile("red.global.add.v4.f32 [%0], {%1, %2, %3, %4};"
                     :: "l"(addr), "f"(v0), "f"(v1), "f"(v2), "f"(v3)
                     : "memory");
    }
    (void)c; (void)r;
}

// ---------------------------------------------------------------------------
// transpose: [B][Y*X][C] scratch -> [B][C][Y*X] output (writes ALL elements)
// ---------------------------------------------------------------------------
__global__ __launch_bounds__(256) void transpose_kernel(float* __restrict__ out) {
    __shared__ float tile[64][C_ + 1];
    int b   = blockIdx.y;
    int yx0 = blockIdx.x * 64;
    const float4* s4 = (const float4*)(g_scratch + ((size_t)b * CELLS_ + yx0) * C_);
    for (int p = threadIdx.x; p < 64 * (C_ / 4); p += 256) {
        int cell = p / (C_ / 4);
        int q    = p - cell * (C_ / 4);
        float4 v = s4[cell * (C_ / 4) + q];
        tile[cell][q*4+0] = v.x; tile[cell][q*4+1] = v.y;
        tile[cell][q*4+2] = v.z; tile[cell][q*4+3] = v.w;
    }
    __syncthreads();
    float* ob = out + (size_t)b * C_ * CELLS_ + yx0;
    for (int p = threadIdx.x; p < 64 * C_; p += 256) {
        int c = p / 64;
        int i = p - c * 64;
        ob[(size_t)c * CELLS_ + i] = tile[i][c];
    }
}

// ---------------------------------------------------------------------------
extern "C" void kernel_launch(void* const* d_in, const int* in_sizes, int n_in,
                              void* d_out, int out_size) {
    const float* ctx    = (const float*)d_in[0];
    const float* dl     = (const float*)d_in[1];
    const float* s2e    = (const float*)d_in[2];
    const float* intrin = (const float*)d_in[3];
    const float* ida    = (const float*)d_in[4];
    const float* bda    = (const float*)d_in[5];
    float* out = (float*)d_out;

    zero_scratch_kernel<<<OUTN_ / 4 / 256, 256>>>();
    prep_kernel<<<1, 32>>>(s2e, intrin, ida, bda);
    lss_main<<<NPIX_, 128>>>(ctx, dl);
    transpose_kernel<<<dim3(CELLS_ / 64, B_), 256>>>(out);
}

// round 9
// speedup vs baseline: 1.7233x; 1.0703x over previous
#include <cuda_runtime.h>
#include <math.h>

#define B_   2
#define N_   6
#define C_   80
#define FH_  16
#define FW_  44
#define D_   112
#define NX_  128
#define NY_  128
#define BN_  (B_*N_)
#define PIX_ (FH_*FW_)          // 704
#define NPIX_ (BN_*PIX_)        // 8448
#define CELLS_ (NX_*NY_)        // 16384
#define OUTN_ (B_*C_*CELLS_)    // 2621440

__device__ float g_comb[BN_][16];    // bda @ s2e @ inv(intrin)
__device__ float g_idainv[BN_][16];  // inv(ida)
__device__ __align__(128) float g_scratch[OUTN_];   // [B][Y*X][C] channel-last accumulator

// ---------------------------------------------------------------------------
// general 4x4 inverse (adjugate, double precision)
// ---------------------------------------------------------------------------
__device__ void inv4x4d(const float* src, double* out) {
    double m[16];
    #pragma unroll
    for (int i = 0; i < 16; i++) m[i] = (double)src[i];
    double inv[16];
    inv[0]  =  m[5]*m[10]*m[15] - m[5]*m[11]*m[14] - m[9]*m[6]*m[15] + m[9]*m[7]*m[14] + m[13]*m[6]*m[11] - m[13]*m[7]*m[10];
    inv[4]  = -m[4]*m[10]*m[15] + m[4]*m[11]*m[14] + m[8]*m[6]*m[15] - m[8]*m[7]*m[14] - m[12]*m[6]*m[11] + m[12]*m[7]*m[10];
    inv[8]  =  m[4]*m[9]*m[15]  - m[4]*m[11]*m[13] - m[8]*m[5]*m[15] + m[8]*m[7]*m[13] + m[12]*m[5]*m[11] - m[12]*m[7]*m[9];
    inv[12] = -m[4]*m[9]*m[14]  + m[4]*m[10]*m[13] + m[8]*m[5]*m[14] - m[8]*m[6]*m[13] - m[12]*m[5]*m[10] + m[12]*m[6]*m[9];
    inv[1]  = -m[1]*m[10]*m[15] + m[1]*m[11]*m[14] + m[9]*m[2]*m[15] - m[9]*m[3]*m[14] - m[13]*m[2]*m[11] + m[13]*m[3]*m[10];
    inv[5]  =  m[0]*m[10]*m[15] - m[0]*m[11]*m[14] - m[8]*m[2]*m[15] + m[8]*m[3]*m[14] + m[12]*m[2]*m[11] - m[12]*m[3]*m[10];
    inv[9]  = -m[0]*m[9]*m[15]  + m[0]*m[11]*m[13] + m[8]*m[1]*m[15] - m[8]*m[3]*m[13] - m[12]*m[1]*m[11] + m[12]*m[3]*m[9];
    inv[13] =  m[0]*m[9]*m[14]  - m[0]*m[10]*m[13] - m[8]*m[1]*m[14] + m[8]*m[2]*m[13] + m[12]*m[1]*m[10] - m[12]*m[2]*m[9];
    inv[2]  =  m[1]*m[6]*m[15]  - m[1]*m[7]*m[14]  - m[5]*m[2]*m[15] + m[5]*m[3]*m[14] + m[13]*m[2]*m[7]  - m[13]*m[3]*m[6];
    inv[6]  = -m[0]*m[6]*m[15]  + m[0]*m[7]*m[14]  + m[4]*m[2]*m[15] - m[4]*m[3]*m[14] - m[12]*m[2]*m[7]  + m[12]*m[3]*m[6];
    inv[10] =  m[0]*m[5]*m[15]  - m[0]*m[7]*m[13]  - m[4]*m[1]*m[15] + m[4]*m[3]*m[13] + m[12]*m[1]*m[7]  - m[12]*m[3]*m[5];
    inv[14] = -m[0]*m[5]*m[14]  + m[0]*m[6]*m[13]  + m[4]*m[1]*m[14] - m[4]*m[2]*m[13] - m[12]*m[1]*m[6]  + m[12]*m[2]*m[5];
    inv[3]  = -m[1]*m[6]*m[11]  + m[1]*m[7]*m[10]  + m[5]*m[2]*m[11] - m[5]*m[3]*m[10] - m[9]*m[2]*m[7]   + m[9]*m[3]*m[6];
    inv[7]  =  m[0]*m[6]*m[11]  - m[0]*m[7]*m[10]  - m[4]*m[2]*m[11] + m[4]*m[3]*m[10] + m[8]*m[2]*m[7]   - m[8]*m[3]*m[6];
    inv[11] = -m[0]*m[5]*m[11]  + m[0]*m[7]*m[9]   + m[4]*m[1]*m[11] - m[4]*m[3]*m[9]  - m[8]*m[1]*m[7]   + m[8]*m[3]*m[5];
    inv[15] =  m[0]*m[5]*m[10]  - m[0]*m[6]*m[9]   - m[4]*m[1]*m[10] + m[4]*m[2]*m[9]  + m[8]*m[1]*m[6]   - m[8]*m[2]*m[5];
    double det = m[0]*inv[0] + m[1]*inv[4] + m[2]*inv[8] + m[3]*inv[12];
    det = 1.0 / det;
    #pragma unroll
    for (int i = 0; i < 16; i++) out[i] = inv[i] * det;
}

__device__ void mm4d(const double* A, const double* Bm, double* Cm) {
    #pragma unroll
    for (int i = 0; i < 4; i++)
        #pragma unroll
        for (int j = 0; j < 4; j++) {
            double s = 0.0;
            #pragma unroll
            for (int k = 0; k < 4; k++) s += A[i*4+k] * Bm[k*4+j];
            Cm[i*4+j] = s;
        }
}

// ---------------------------------------------------------------------------
__global__ void prep_kernel(const float* __restrict__ s2e,
                            const float* __restrict__ intrin,
                            const float* __restrict__ ida,
                            const float* __restrict__ bda) {
    int i = threadIdx.x;
    if (i >= BN_) return;
    int b = i / N_;
    double Mi[16], Ii[16], S[16], Bd[16], T[16], Cm[16];
    inv4x4d(intrin + i*16, Mi);
    inv4x4d(ida + i*16, Ii);
    #pragma unroll
    for (int k = 0; k < 16; k++) { S[k] = (double)s2e[i*16 + k]; Bd[k] = (double)bda[b*16 + k]; }
    mm4d(S, Mi, T);
    mm4d(Bd, T, Cm);
    #pragma unroll
    for (int k = 0; k < 16; k++) { g_comb[i][k] = (float)Cm[k]; g_idainv[i][k] = (float)Ii[k]; }
}

__global__ __launch_bounds__(256) void zero_scratch_kernel() {
    int i = blockIdx.x * blockDim.x + threadIdx.x;
    ((float4*)g_scratch)[i] = make_float4(0.f, 0.f, 0.f, 0.f);
}

// ---------------------------------------------------------------------------
// main: one CTA (128 threads = 4 warps) per feature-map pixel.
//   warp-shfl softmax, per-pixel quadratic geometry g(d)=A+Bd+Cd^2,
//   parallel head-flag run merge, red.v4 scatter into channel-last scratch.
// ---------------------------------------------------------------------------
__global__ __launch_bounds__(128) void lss_main(const float* __restrict__ ctx,
                                                const float* __restrict__ dl) {
    int pix = blockIdx.x;               // bn*704 + h*44 + w
    int bn  = pix / PIX_;
    int hw  = pix - bn * PIX_;
    int h   = hw / FW_;
    int w   = hw - h * FW_;
    int b   = bn / N_;
    int tid = threadIdx.x;
    int lane = tid & 31, wrp = tid >> 5;

    __shared__ float sctx[C_];
    __shared__ float sw[D_];
    __shared__ int   slin[D_];
    __shared__ float spmax[4];
    __shared__ float spsum[4];
    __shared__ int   s_rlin[D_];
    __shared__ float s_rw[D_];
    __shared__ int   s_nr;
    __shared__ float s_ab[8];           // a0..a3, b0..b3
    __shared__ float sA[3], sB[3], sC[3];

    if (tid == 0) s_nr = 0;
    if (tid < C_) sctx[tid] = ctx[(bn * C_ + tid) * PIX_ + hw];

    // per-pixel affine coefficients of p(d) = idainv @ (u, v, d, 1)
    if (tid < 4) {
        float u = (703.0f / 43.0f) * (float)w;     // linspace(0,703,44)
        float v = (float)(17 * h);                 // linspace(0,255,16), exact
        const float* Ii = g_idainv[bn];
        s_ab[tid]     = Ii[tid*4+0]*u + Ii[tid*4+1]*v + Ii[tid*4+3];   // a_i
        s_ab[tid + 4] = Ii[tid*4+2];                                   // b_i
    }

    // ---- softmax over D=112 (warp shfl + 4-word combine) ----
    float l = (tid < D_) ? dl[(bn * D_ + tid) * PIX_ + hw] : -1e30f;
    float m = l;
    #pragma unroll
    for (int s = 16; s > 0; s >>= 1) m = fmaxf(m, __shfl_xor_sync(0xffffffffu, m, s));
    if (lane == 0) spmax[wrp] = m;
    __syncthreads();

    // quadratic coefficients of g(d) = A + B d + C d^2 (threads 0..2, one axis each)
    if (tid < 3) {
        const float* Cm = g_comb[bn] + tid * 4;
        float a0 = s_ab[0], a1 = s_ab[1], a2 = s_ab[2], a3 = s_ab[3];
        float b0 = s_ab[4], b1 = s_ab[5], b2 = s_ab[6], b3 = s_ab[7];
        float A = Cm[0]*(a0*a2) + Cm[1]*(a1*a2) + Cm[2]*a2 + Cm[3]*a3;
        float Bc = Cm[0]*(a0*b2 + b0*a2) + Cm[1]*(a1*b2 + b1*a2) + Cm[2]*b2 + Cm[3]*b3;
        float Cq = Cm[0]*(b0*b2) + Cm[1]*(b1*b2);
        const float LO[3] = { -50.8f - 0.4f, -50.8f - 0.4f, -1.0f - 4.0f };
        sA[tid] = A - LO[tid];
        sB[tid] = Bc;
        sC[tid] = Cq;
    }

    float mx = fmaxf(fmaxf(spmax[0], spmax[1]), fmaxf(spmax[2], spmax[3]));
    float e = (tid < D_) ? __expf(l - mx) : 0.0f;
    float sum = e;
    #pragma unroll
    for (int s = 16; s > 0; s >>= 1) sum += __shfl_xor_sync(0xffffffffu, sum, s);
    if (lane == 0) spsum[wrp] = sum;
    __syncthreads();
    float rinv = 1.0f / (spsum[0] + spsum[1] + spsum[2] + spsum[3]);

    // ---- geometry & voxel index, one depth bin per thread (quadratic form) ----
    if (tid < D_) {
        sw[tid] = e * rinv;
        float dd = 2.25f + 0.5f * (float)tid;      // exact
        const float INV08 = 1.0f / 0.8f;           // compile-time rn
        float gx = fmaf(dd, fmaf(dd, sC[0], sB[0]), sA[0]);
        float gy = fmaf(dd, fmaf(dd, sC[1], sB[1]), sA[1]);
        float gz = fmaf(dd, fmaf(dd, sC[2], sB[2]), sA[2]);
        int ix = __float2int_rd(gx * INV08);
        int iy = __float2int_rd(gy * INV08);
        int iz = __float2int_rd(gz * 0.125f);      // /8.0 == *0.125 bit-exact
        bool valid = ((unsigned)ix < (unsigned)NX_) && ((unsigned)iy < (unsigned)NY_) && (iz == 0);
        slin[tid] = valid ? (iy * NX_ + ix) : -1;
    }
    __syncthreads();

    // ---- parallel run merge: head threads walk their run (avg 1.6 steps) ----
    if (tid < D_) {
        int li = slin[tid];
        bool head = (li >= 0) && (tid == 0 || slin[tid - 1] != li);
        if (head) {
            float s = sw[tid];
            int k = tid + 1;
            while (k < D_ && slin[k] == li) { s += sw[k]; k++; }
            int slot = atomicAdd(&s_nr, 1);
            s_rlin[slot] = li;
            s_rw[slot]   = s;
        }
    }
    __syncthreads();

    int nr = s_nr;
    if (nr == 0) return;

    // ---- scatter: nr runs x 20 float4 quads into channel-last scratch ----
    float* sbase = g_scratch + (size_t)b * (CELLS_ * C_);
    int total = nr * (C_ / 4);
    for (int p = tid; p < total; p += 128) {
        int rr = p / (C_ / 4);
        int q4 = p - rr * (C_ / 4);
        float wgt = s_rw[rr];
        float v0 = wgt * sctx[q4*4 + 0];
        float v1 = wgt * sctx[q4*4 + 1];
        float v2 = wgt * sctx[q4*4 + 2];
        float v3 = wgt * sctx[q4*4 + 3];
        float* addr = sbase + (size_t)s_rlin[rr] * C_ + q4 * 4;
        asm volatile("red.global.add.v4.f32 [%0], {%1, %2, %3, %4};"
                     :: "l"(addr), "f"(v0), "f"(v1), "f"(v2), "f"(v3)
                     : "memory");
    }
}

// ---------------------------------------------------------------------------
// transpose: [B][Y*X][C] scratch -> [B][C][Y*X] output (writes ALL elements)
// ---------------------------------------------------------------------------
__global__ __launch_bounds__(256) void transpose_kernel(float* __restrict__ out) {
    __shared__ float tile[64][C_ + 1];
    int b   = blockIdx.y;
    int yx0 = blockIdx.x * 64;
    const float4* s4 = (const float4*)(g_scratch + ((size_t)b * CELLS_ + yx0) * C_);
    for (int p = threadIdx.x; p < 64 * (C_ / 4); p += 256) {
        int cell = p / (C_ / 4);
        int q    = p - cell * (C_ / 4);
        float4 v = s4[cell * (C_ / 4) + q];
        tile[cell][q*4+0] = v.x; tile[cell][q*4+1] = v.y;
        tile[cell][q*4+2] = v.z; tile[cell][q*4+3] = v.w;
    }
    __syncthreads();
    // vectorized output: each task = (channel c, group of 4 consecutive cells)
    float* ob = out + (size_t)b * C_ * CELLS_ + yx0;
    for (int p = threadIdx.x; p < C_ * (64 / 4); p += 256) {
        int c  = p / (64 / 4);
        int i4 = (p - c * (64 / 4)) * 4;
        float4 v = make_float4(tile[i4+0][c], tile[i4+1][c], tile[i4+2][c], tile[i4+3][c]);
        *(float4*)(ob + (size_t)c * CELLS_ + i4) = v;
    }
}

// ---------------------------------------------------------------------------
extern "C" void kernel_launch(void* const* d_in, const int* in_sizes, int n_in,
                              void* d_out, int out_size) {
    const float* ctx    = (const float*)d_in[0];
    const float* dl     = (const float*)d_in[1];
    const float* s2e    = (const float*)d_in[2];
    const float* intrin = (const float*)d_in[3];
    const float* ida    = (const float*)d_in[4];
    const float* bda    = (const float*)d_in[5];
    float* out = (float*)d_out;

    zero_scratch_kernel<<<OUTN_ / 4 / 256, 256>>>();
    prep_kernel<<<1, 32>>>(s2e, intrin, ida, bda);
    lss_main<<<NPIX_, 128>>>(ctx, dl);
    transpose_kernel<<<dim3(CELLS_ / 64, B_), 256>>>(out);
}

// round 10
// speedup vs baseline: 1.8717x; 1.0861x over previous
#include <cuda_runtime.h>
#include <math.h>

#define B_   2
#define N_   6
#define C_   80
#define FH_  16
#define FW_  44
#define D_   112
#define NX_  128
#define NY_  128
#define BN_  (B_*N_)
#define PIX_ (FH_*FW_)          // 704
#define NPIX_ (BN_*PIX_)        // 8448
#define CELLS_ (NX_*NY_)        // 16384
#define OUTN_ (B_*C_*CELLS_)    // 2621440
#define CAP_  512               // smem hash capacity (cells per column-CTA)

__device__ float g_comb[BN_][16];    // bda @ s2e @ inv(intrin)
__device__ float g_idainv[BN_][16];  // inv(ida)
__device__ __align__(128) float g_scratch[OUTN_];   // [B][Y*X][C] channel-last accumulator

// ---------------------------------------------------------------------------
// general 4x4 inverse (adjugate, double precision)
// ---------------------------------------------------------------------------
__device__ void inv4x4d(const float* src, double* out) {
    double m[16];
    #pragma unroll
    for (int i = 0; i < 16; i++) m[i] = (double)src[i];
    double inv[16];
    inv[0]  =  m[5]*m[10]*m[15] - m[5]*m[11]*m[14] - m[9]*m[6]*m[15] + m[9]*m[7]*m[14] + m[13]*m[6]*m[11] - m[13]*m[7]*m[10];
    inv[4]  = -m[4]*m[10]*m[15] + m[4]*m[11]*m[14] + m[8]*m[6]*m[15] - m[8]*m[7]*m[14] - m[12]*m[6]*m[11] + m[12]*m[7]*m[10];
    inv[8]  =  m[4]*m[9]*m[15]  - m[4]*m[11]*m[13] - m[8]*m[5]*m[15] + m[8]*m[7]*m[13] + m[12]*m[5]*m[11] - m[12]*m[7]*m[9];
    inv[12] = -m[4]*m[9]*m[14]  + m[4]*m[10]*m[13] + m[8]*m[5]*m[14] - m[8]*m[6]*m[13] - m[12]*m[5]*m[10] + m[12]*m[6]*m[9];
    inv[1]  = -m[1]*m[10]*m[15] + m[1]*m[11]*m[14] + m[9]*m[2]*m[15] - m[9]*m[3]*m[14] - m[13]*m[2]*m[11] + m[13]*m[3]*m[10];
    inv[5]  =  m[0]*m[10]*m[15] - m[0]*m[11]*m[14] - m[8]*m[2]*m[15] + m[8]*m[3]*m[14] + m[12]*m[2]*m[11] - m[12]*m[3]*m[10];
    inv[9]  = -m[0]*m[9]*m[15]  + m[0]*m[11]*m[13] + m[8]*m[1]*m[15] - m[8]*m[3]*m[13] - m[12]*m[1]*m[11] + m[12]*m[3]*m[9];
    inv[13] =  m[0]*m[9]*m[14]  - m[0]*m[10]*m[13] - m[8]*m[1]*m[14] + m[8]*m[2]*m[13] + m[12]*m[1]*m[10] - m[12]*m[2]*m[9];
    inv[2]  =  m[1]*m[6]*m[15]  - m[1]*m[7]*m[14]  - m[5]*m[2]*m[15] + m[5]*m[3]*m[14] + m[13]*m[2]*m[7]  - m[13]*m[3]*m[6];
    inv[6]  = -m[0]*m[6]*m[15]  + m[0]*m[7]*m[14]  + m[4]*m[2]*m[15] - m[4]*m[3]*m[14] - m[12]*m[2]*m[7]  + m[12]*m[3]*m[6];
    inv[10] =  m[0]*m[5]*m[15]  - m[0]*m[7]*m[13]  - m[4]*m[1]*m[15] + m[4]*m[3]*m[13] + m[12]*m[1]*m[7]  - m[12]*m[3]*m[5];
    inv[14] = -m[0]*m[5]*m[14]  + m[0]*m[6]*m[13]  + m[4]*m[1]*m[14] - m[4]*m[2]*m[13] - m[12]*m[1]*m[6]  + m[12]*m[2]*m[5];
    inv[3]  = -m[1]*m[6]*m[11]  + m[1]*m[7]*m[10]  + m[5]*m[2]*m[11] - m[5]*m[3]*m[10] - m[9]*m[2]*m[7]   + m[9]*m[3]*m[6];
    inv[7]  =  m[0]*m[6]*m[11]  - m[0]*m[7]*m[10]  - m[4]*m[2]*m[11] + m[4]*m[3]*m[10] + m[8]*m[2]*m[7]   - m[8]*m[3]*m[6];
    inv[11] = -m[0]*m[5]*m[11]  + m[0]*m[7]*m[9]   + m[4]*m[1]*m[11] - m[4]*m[3]*m[9]  - m[8]*m[1]*m[7]   + m[8]*m[3]*m[5];
    inv[15] =  m[0]*m[5]*m[10]  - m[0]*m[6]*m[9]   - m[4]*m[1]*m[10] + m[4]*m[2]*m[9]  + m[8]*m[1]*m[6]   - m[8]*m[2]*m[5];
    double det = m[0]*inv[0] + m[1]*inv[4] + m[2]*inv[8] + m[3]*inv[12];
    det = 1.0 / det;
    #pragma unroll
    for (int i = 0; i < 16; i++) out[i] = inv[i] * det;
}

__device__ void mm4d(const double* A, const double* Bm, double* Cm) {
    #pragma unroll
    for (int i = 0; i < 4; i++)
        #pragma unroll
        for (int j = 0; j < 4; j++) {
            double s = 0.0;
            #pragma unroll
            for (int k = 0; k < 4; k++) s += A[i*4+k] * Bm[k*4+j];
            Cm[i*4+j] = s;
        }
}

// ---------------------------------------------------------------------------
__global__ void prep_kernel(const float* __restrict__ s2e,
                            const float* __restrict__ intrin,
                            const float* __restrict__ ida,
                            const float* __restrict__ bda) {
    int i = threadIdx.x;
    if (i >= BN_) return;
    int b = i / N_;
    double Mi[16], Ii[16], S[16], Bd[16], T[16], Cm[16];
    inv4x4d(intrin + i*16, Mi);
    inv4x4d(ida + i*16, Ii);
    #pragma unroll
    for (int k = 0; k < 16; k++) { S[k] = (double)s2e[i*16 + k]; Bd[k] = (double)bda[b*16 + k]; }
    mm4d(S, Mi, T);
    mm4d(Bd, T, Cm);
    #pragma unroll
    for (int k = 0; k < 16; k++) { g_comb[i][k] = (float)Cm[k]; g_idainv[i][k] = (float)Ii[k]; }
}

__global__ __launch_bounds__(256) void zero_scratch_kernel() {
    int i = blockIdx.x * blockDim.x + threadIdx.x;
    ((float4*)g_scratch)[i] = make_float4(0.f, 0.f, 0.f, 0.f);
}

// ---------------------------------------------------------------------------
// column-fused main: one CTA (256 thr, 8 warps) per (bn, w) image column.
//   Each warp: 2 pixels (h). Register softmax -> quadratic geometry ->
//   smem hash accumulate (cell -> per-pixel weight sums) -> one red.v4 set
//   per DISTINCT cell (~13x fewer global atomics than per-pixel scatter).
// ---------------------------------------------------------------------------
__global__ __launch_bounds__(256) void lss_main(const float* __restrict__ ctx,
                                                const float* __restrict__ dl) {
    int blk = blockIdx.x;               // bn*FW_ + w
    int bn  = blk / FW_;
    int w   = blk - bn * FW_;
    int b   = bn / N_;
    int tid = threadIdx.x;
    int lane = tid & 31, wrp = tid >> 5;

    __shared__ int   skey[CAP_];
    __shared__ float swsum[CAP_ * FH_];     // [slot][pixel]
    __shared__ float sctx[FH_][C_];         // [pixel][channel]
    __shared__ int   slist[CAP_];
    __shared__ int   s_n;

    // init
    for (int i = tid; i < CAP_; i += 256) skey[i] = -1;
    for (int i = tid; i < CAP_ * FH_; i += 256) swsum[i] = 0.f;
    if (tid == 0) s_n = 0;

    // ctx for all 16 pixels of this column (channel-major source, scattered)
    for (int i = tid; i < FH_ * C_; i += 256) {
        int p = i / C_, c = i - p * C_;
        sctx[p][c] = ctx[(bn * C_ + c) * PIX_ + p * FW_ + w];
    }
    __syncthreads();

    float* sbase = g_scratch + (size_t)b * (CELLS_ * C_);

    // ---- per-warp: 2 pixels each ----
    for (int p = wrp; p < FH_; p += 8) {
        int hw = p * FW_ + w;
        const float* dlp = dl + (size_t)(bn * D_) * PIX_ + hw;

        // register softmax over D=112 (4 depths per lane)
        float l0 = dlp[(size_t)lane * PIX_];
        float l1 = dlp[(size_t)(lane + 32) * PIX_];
        float l2 = dlp[(size_t)(lane + 64) * PIX_];
        float l3 = (lane < 16) ? dlp[(size_t)(lane + 96) * PIX_] : -1e30f;
        float m = fmaxf(fmaxf(l0, l1), fmaxf(l2, l3));
        #pragma unroll
        for (int s = 16; s > 0; s >>= 1) m = fmaxf(m, __shfl_xor_sync(0xffffffffu, m, s));
        float e0 = __expf(l0 - m), e1 = __expf(l1 - m), e2 = __expf(l2 - m);
        float e3 = (lane < 16) ? __expf(l3 - m) : 0.f;
        float sum = e0 + e1 + e2 + e3;
        #pragma unroll
        for (int s = 16; s > 0; s >>= 1) sum += __shfl_xor_sync(0xffffffffu, sum, s);
        float rinv = 1.0f / sum;

        // per-pixel quadratic geometry coefficients (lane-redundant, cheap)
        float u = (703.0f / 43.0f) * (float)w;   // linspace(0,703,44)
        float v = (float)(17 * p);               // linspace(0,255,16), exact
        const float* Ii = g_idainv[bn];
        float a0 = Ii[0]*u  + Ii[1]*v  + Ii[3];
        float a1 = Ii[4]*u  + Ii[5]*v  + Ii[7];
        float a2 = Ii[8]*u  + Ii[9]*v  + Ii[11];
        float a3 = Ii[12]*u + Ii[13]*v + Ii[15];
        float b0 = Ii[2], b1 = Ii[6], b2 = Ii[10], b3 = Ii[14];
        const float* Cm = g_comb[bn];
        float Ax[3], Bx[3], Cx[3];
        const float LO[3] = { -50.8f - 0.4f, -50.8f - 0.4f, -1.0f - 4.0f };
        #pragma unroll
        for (int ax = 0; ax < 3; ax++) {
            const float* Cr = Cm + ax * 4;
            Ax[ax] = Cr[0]*(a0*a2) + Cr[1]*(a1*a2) + Cr[2]*a2 + Cr[3]*a3 - LO[ax];
            Bx[ax] = Cr[0]*(a0*b2 + b0*a2) + Cr[1]*(a1*b2 + b1*a2) + Cr[2]*b2 + Cr[3]*b3;
            Cx[ax] = Cr[0]*(b0*b2) + Cr[1]*(b1*b2);
        }

        float ee[4] = { e0, e1, e2, e3 };
        #pragma unroll
        for (int r = 0; r < 4; r++) {
            int di = lane + 32 * r;
            if (r == 3 && lane >= 16) continue;
            float wgt = ee[r] * rinv;
            float dd = 2.25f + 0.5f * (float)di;       // exact
            const float INV08 = 1.0f / 0.8f;
            float gx = fmaf(dd, fmaf(dd, Cx[0], Bx[0]), Ax[0]);
            float gy = fmaf(dd, fmaf(dd, Cx[1], Bx[1]), Ax[1]);
            float gz = fmaf(dd, fmaf(dd, Cx[2], Bx[2]), Ax[2]);
            int ix = __float2int_rd(gx * INV08);
            int iy = __float2int_rd(gy * INV08);
            int iz = __float2int_rd(gz * 0.125f);      // /8.0 bit-exact
            if (((unsigned)ix < (unsigned)NX_) && ((unsigned)iy < (unsigned)NY_) && (iz == 0)) {
                int cell = iy * NX_ + ix;
                // hash insert / find
                unsigned hsh = ((unsigned)cell * 2654435761u) >> 7;
                int slot = -1;
                for (int probe = 0; probe < CAP_; probe++) {
                    int sidx = (int)((hsh + probe) & (CAP_ - 1));
                    int k = skey[sidx];
                    if (k == cell) { slot = sidx; break; }
                    if (k == -1) {
                        int old = atomicCAS(&skey[sidx], -1, cell);
                        if (old == -1) {
                            int li = atomicAdd(&s_n, 1);
                            slist[li] = sidx;
                            slot = sidx; break;
                        }
                        if (old == cell) { slot = sidx; break; }
                    }
                }
                if (slot >= 0) {
                    atomicAdd(&swsum[slot * FH_ + p], wgt);
                } else {
                    // table full (shouldn't happen for this data): direct scatter
                    float* ad = sbase + (size_t)cell * C_;
                    #pragma unroll
                    for (int q = 0; q < C_ / 4; q++) {
                        float v0 = wgt * sctx[p][q*4+0];
                        float v1 = wgt * sctx[p][q*4+1];
                        float v2 = wgt * sctx[p][q*4+2];
                        float v3 = wgt * sctx[p][q*4+3];
                        asm volatile("red.global.add.v4.f32 [%0], {%1, %2, %3, %4};"
                                     :: "l"(ad + q*4), "f"(v0), "f"(v1), "f"(v2), "f"(v3)
                                     : "memory");
                    }
                }
            }
        }
    }
    __syncthreads();

    // ---- phase 3: one red.v4 per (distinct cell, channel quad) ----
    int n = s_n;
    int total = n * (C_ / 4);
    for (int t = tid; t < total; t += 256) {
        int eidx = t / (C_ / 4);
        int q    = t - eidx * (C_ / 4);
        int slot = slist[eidx];
        int cell = skey[slot];
        const float* wp = &swsum[slot * FH_];
        float acc0 = 0.f, acc1 = 0.f, acc2 = 0.f, acc3 = 0.f;
        #pragma unroll
        for (int p = 0; p < FH_; p++) {
            float wv = wp[p];
            acc0 = fmaf(wv, sctx[p][q*4+0], acc0);
            acc1 = fmaf(wv, sctx[p][q*4+1], acc1);
            acc2 = fmaf(wv, sctx[p][q*4+2], acc2);
            acc3 = fmaf(wv, sctx[p][q*4+3], acc3);
        }
        float* addr = sbase + (size_t)cell * C_ + q * 4;
        asm volatile("red.global.add.v4.f32 [%0], {%1, %2, %3, %4};"
                     :: "l"(addr), "f"(acc0), "f"(acc1), "f"(acc2), "f"(acc3)
                     : "memory");
    }
}

// ---------------------------------------------------------------------------
// transpose: [B][Y*X][C] scratch -> [B][C][Y*X] output (writes ALL elements)
// 32 cells per CTA, 128 threads -> 1024 CTAs (grid-starved at 512 before)
// ---------------------------------------------------------------------------
__global__ __launch_bounds__(128) void transpose_kernel(float* __restrict__ out) {
    __shared__ float tile[32][C_ + 1];
    int b   = blockIdx.y;
    int yx0 = blockIdx.x * 32;
    const float4* s4 = (const float4*)(g_scratch + ((size_t)b * CELLS_ + yx0) * C_);
    for (int p = threadIdx.x; p < 32 * (C_ / 4); p += 128) {
        int cell = p / (C_ / 4);
        int q    = p - cell * (C_ / 4);
        float4 v = s4[cell * (C_ / 4) + q];
        tile[cell][q*4+0] = v.x; tile[cell][q*4+1] = v.y;
        tile[cell][q*4+2] = v.z; tile[cell][q*4+3] = v.w;
    }
    __syncthreads();
    float* ob = out + (size_t)b * C_ * CELLS_ + yx0;
    for (int p = threadIdx.x; p < C_ * 8; p += 128) {
        int c  = p / 8;
        int i4 = (p - c * 8) * 4;
        float4 v = make_float4(tile[i4+0][c], tile[i4+1][c], tile[i4+2][c], tile[i4+3][c]);
        *(float4*)(ob + (size_t)c * CELLS_ + i4) = v;
    }
}

// ---------------------------------------------------------------------------
extern "C" void kernel_launch(void* const* d_in, const int* in_sizes, int n_in,
                              void* d_out, int out_size) {
    const float* ctx    = (const float*)d_in[0];
    const float* dl     = (const float*)d_in[1];
    const float* s2e    = (const float*)d_in[2];
    const float* intrin = (const float*)d_in[3];
    const float* ida    = (const float*)d_in[4];
    const float* bda    = (const float*)d_in[5];
    float* out = (float*)d_out;

    zero_scratch_kernel<<<OUTN_ / 4 / 256, 256>>>();
    prep_kernel<<<1, 32>>>(s2e, intrin, ida, bda);
    lss_main<<<BN_ * FW_, 256>>>(ctx, dl);
    transpose_kernel<<<dim3(CELLS_ / 32, B_), 128>>>(out);
}

// round 14
// speedup vs baseline: 2.5946x; 1.3862x over previous
#include <cuda_runtime.h>
#include <math.h>

#define B_   2
#define N_   6
#define C_   80
#define FH_  16
#define FW_  44
#define D_   112
#define NX_  128
#define NY_  128
#define BN_  (B_*N_)
#define PIX_ (FH_*FW_)          // 704
#define NPIX_ (BN_*PIX_)        // 8448
#define CELLS_ (NX_*NY_)        // 16384
#define OUTN_ (B_*C_*CELLS_)    // 2621440
#define CAP_  512               // smem hash capacity (cells per column-CTA)

__device__ float g_comb[BN_][16];    // bda @ s2e @ inv(intrin)
__device__ float g_idainv[BN_][16];  // inv(ida)
__device__ __align__(128) float g_scratch[OUTN_];   // [B][Y*X][C] channel-last accumulator

// ---------------------------------------------------------------------------
// parallel prep: one block, 384 threads.
//   phase 1: 384 threads = (2 inverses) x (12 matrices) x (16 adjugate entries)
//   phase 2: 24 threads compute dets
//   phase 3: scale adjugates by 1/det
//   phase 4: T = s2e @ inv(intrin)      (192 threads, one entry each)
//   phase 5: comb = bda @ T, write outputs
// All math in double; serial FP64 depth ~25 ops (was ~700 on one warp).
// ---------------------------------------------------------------------------
__global__ __launch_bounds__(384) void prep_kernel(const float* __restrict__ s2e,
                                                   const float* __restrict__ intrin,
                                                   const float* __restrict__ ida,
                                                   const float* __restrict__ bda) {
    __shared__ double adj[2][BN_][16];    // scaled adjugates (inverses)
    __shared__ double rdet[2][BN_];
    __shared__ double Tm[BN_][16];
    int t = threadIdx.x;

    // phase 1: adjugate entries
    if (t < 2 * BN_ * 16) {
        int pair = t / (BN_ * 16);
        int rem  = t - pair * (BN_ * 16);
        int i    = rem >> 4;
        int k    = rem & 15;
        const float* src = (pair ? ida : intrin) + i * 16;
        double m[16];
        #pragma unroll
        for (int j = 0; j < 16; j++) m[j] = (double)src[j];
        int r = k >> 2, c = k & 3;
        // inv[k] = adj[r][c] = (-1)^(r+c) * det3(minor deleting row c, col r)
        int rr[3], cc[3], nr = 0, nc = 0;
        #pragma unroll
        for (int j = 0; j < 4; j++) { if (j != c) rr[nr++] = j; }
        #pragma unroll
        for (int j = 0; j < 4; j++) { if (j != r) cc[nc++] = j; }
        double a = m[rr[0]*4+cc[0]], bb = m[rr[0]*4+cc[1]], cx = m[rr[0]*4+cc[2]];
        double d = m[rr[1]*4+cc[0]], e  = m[rr[1]*4+cc[1]], f  = m[rr[1]*4+cc[2]];
        double g = m[rr[2]*4+cc[0]], h  = m[rr[2]*4+cc[1]], ii = m[rr[2]*4+cc[2]];
        double det3 = a*(e*ii - f*h) - bb*(d*ii - f*g) + cx*(d*h - e*g);
        adj[pair][i][k] = (((r + c) & 1) ? -det3 : det3);
    }
    __syncthreads();

    // phase 2: determinants (det = sum_j m[0][j] * adj[j][0])
    if (t < 2 * BN_) {
        int pair = t / BN_;
        int i    = t - pair * BN_;
        const float* src = (pair ? ida : intrin) + i * 16;
        double det = 0.0;
        #pragma unroll
        for (int j = 0; j < 4; j++) det += (double)src[j] * adj[pair][i][j*4];
        rdet[pair][i] = 1.0 / det;
    }
    __syncthreads();

    // phase 3: scale
    if (t < 2 * BN_ * 16) {
        int pair = t / (BN_ * 16);
        int rem  = t - pair * (BN_ * 16);
        int i    = rem >> 4;
        int k    = rem & 15;
        adj[pair][i][k] *= rdet[pair][i];
    }
    __syncthreads();

    // phase 4: T = s2e @ inv(intrin)
    if (t < BN_ * 16) {
        int i = t >> 4, k = t & 15;
        int r = k >> 2, c = k & 3;
        double s = 0.0;
        #pragma unroll
        for (int j = 0; j < 4; j++) s += (double)s2e[i*16 + r*4 + j] * adj[0][i][j*4 + c];
        Tm[i][k] = s;
    }
    __syncthreads();

    // phase 5: comb = bda @ T; write outputs
    if (t < BN_ * 16) {
        int i = t >> 4, k = t & 15;
        int r = k >> 2, c = k & 3;
        int b = i / N_;
        double s = 0.0;
        #pragma unroll
        for (int j = 0; j < 4; j++) s += (double)bda[b*16 + r*4 + j] * Tm[i][j*4 + c];
        g_comb[i][k]   = (float)s;
        g_idainv[i][k] = (float)adj[1][i][k];
    }
}

__global__ __launch_bounds__(256) void zero_scratch_kernel() {
    int i = blockIdx.x * blockDim.x + threadIdx.x;
    ((float4*)g_scratch)[i] = make_float4(0.f, 0.f, 0.f, 0.f);
}

// ---------------------------------------------------------------------------
// column-fused main: one CTA (256 thr, 8 warps) per (bn, w) image column.
//   Each warp: 2 pixels (h). Register softmax -> quadratic geometry ->
//   smem hash accumulate (cell -> per-pixel weight sums) -> one red.v4 set
//   per DISTINCT cell (~13x fewer global atomics than per-pixel scatter).
// ---------------------------------------------------------------------------
__global__ __launch_bounds__(256) void lss_main(const float* __restrict__ ctx,
                                                const float* __restrict__ dl) {
    int blk = blockIdx.x;               // bn*FW_ + w
    int bn  = blk / FW_;
    int w   = blk - bn * FW_;
    int b   = bn / N_;
    int tid = threadIdx.x;
    int lane = tid & 31, wrp = tid >> 5;

    __shared__ int   skey[CAP_];
    __shared__ float swsum[CAP_ * FH_];     // [slot][pixel]
    __shared__ float sctx[FH_][C_];         // [pixel][channel]
    __shared__ int   slist[CAP_];
    __shared__ int   s_n;

    // init
    for (int i = tid; i < CAP_; i += 256) skey[i] = -1;
    for (int i = tid; i < CAP_ * FH_; i += 256) swsum[i] = 0.f;
    if (tid == 0) s_n = 0;

    // ctx for all 16 pixels of this column (channel-major source, scattered)
    for (int i = tid; i < FH_ * C_; i += 256) {
        int p = i / C_, c = i - p * C_;
        sctx[p][c] = ctx[(bn * C_ + c) * PIX_ + p * FW_ + w];
    }
    __syncthreads();

    float* sbase = g_scratch + (size_t)b * (CELLS_ * C_);

    // ---- per-warp: 2 pixels each ----
    for (int p = wrp; p < FH_; p += 8) {
        int hw = p * FW_ + w;
        const float* dlp = dl + (size_t)(bn * D_) * PIX_ + hw;

        // register softmax over D=112 (4 depths per lane)
        float l0 = dlp[(size_t)lane * PIX_];
        float l1 = dlp[(size_t)(lane + 32) * PIX_];
        float l2 = dlp[(size_t)(lane + 64) * PIX_];
        float l3 = (lane < 16) ? dlp[(size_t)(lane + 96) * PIX_] : -1e30f;
        float m = fmaxf(fmaxf(l0, l1), fmaxf(l2, l3));
        #pragma unroll
        for (int s = 16; s > 0; s >>= 1) m = fmaxf(m, __shfl_xor_sync(0xffffffffu, m, s));
        float e0 = __expf(l0 - m), e1 = __expf(l1 - m), e2 = __expf(l2 - m);
        float e3 = (lane < 16) ? __expf(l3 - m) : 0.f;
        float sum = e0 + e1 + e2 + e3;
        #pragma unroll
        for (int s = 16; s > 0; s >>= 1) sum += __shfl_xor_sync(0xffffffffu, sum, s);
        float rinv = 1.0f / sum;

        // per-pixel quadratic geometry coefficients (lane-redundant, cheap)
        float u = (703.0f / 43.0f) * (float)w;   // linspace(0,703,44)
        float v = (float)(17 * p);               // linspace(0,255,16), exact
        const float* Ii = g_idainv[bn];
        float a0 = Ii[0]*u  + Ii[1]*v  + Ii[3];
        float a1 = Ii[4]*u  + Ii[5]*v  + Ii[7];
        float a2 = Ii[8]*u  + Ii[9]*v  + Ii[11];
        float a3 = Ii[12]*u + Ii[13]*v + Ii[15];
        float b0 = Ii[2], b1 = Ii[6], b2 = Ii[10], b3 = Ii[14];
        const float* Cm = g_comb[bn];
        float Ax[3], Bx[3], Cx[3];
        const float LO[3] = { -50.8f - 0.4f, -50.8f - 0.4f, -1.0f - 4.0f };
        #pragma unroll
        for (int ax = 0; ax < 3; ax++) {
            const float* Cr = Cm + ax * 4;
            Ax[ax] = Cr[0]*(a0*a2) + Cr[1]*(a1*a2) + Cr[2]*a2 + Cr[3]*a3 - LO[ax];
            Bx[ax] = Cr[0]*(a0*b2 + b0*a2) + Cr[1]*(a1*b2 + b1*a2) + Cr[2]*b2 + Cr[3]*b3;
            Cx[ax] = Cr[0]*(b0*b2) + Cr[1]*(b1*b2);
        }

        float ee[4] = { e0, e1, e2, e3 };
        #pragma unroll
        for (int r = 0; r < 4; r++) {
            int di = lane + 32 * r;
            if (r == 3 && lane >= 16) continue;
            float wgt = ee[r] * rinv;
            float dd = 2.25f + 0.5f * (float)di;       // exact
            const float INV08 = 1.0f / 0.8f;
            float gx = fmaf(dd, fmaf(dd, Cx[0], Bx[0]), Ax[0]);
            float gy = fmaf(dd, fmaf(dd, Cx[1], Bx[1]), Ax[1]);
            float gz = fmaf(dd, fmaf(dd, Cx[2], Bx[2]), Ax[2]);
            int ix = __float2int_rd(gx * INV08);
            int iy = __float2int_rd(gy * INV08);
            int iz = __float2int_rd(gz * 0.125f);      // /8.0 bit-exact
            if (((unsigned)ix < (unsigned)NX_) && ((unsigned)iy < (unsigned)NY_) && (iz == 0)) {
                int cell = iy * NX_ + ix;
                // hash insert / find
                unsigned hsh = ((unsigned)cell * 2654435761u) >> 7;
                int slot = -1;
                for (int probe = 0; probe < CAP_; probe++) {
                    int sidx = (int)((hsh + probe) & (CAP_ - 1));
                    int k = skey[sidx];
                    if (k == cell) { slot = sidx; break; }
                    if (k == -1) {
                        int old = atomicCAS(&skey[sidx], -1, cell);
                        if (old == -1) {
                            int li = atomicAdd(&s_n, 1);
                            slist[li] = sidx;
                            slot = sidx; break;
                        }
                        if (old == cell) { slot = sidx; break; }
                    }
                }
                if (slot >= 0) {
                    atomicAdd(&swsum[slot * FH_ + p], wgt);
                } else {
                    // table full (shouldn't happen for this data): direct scatter
                    float* ad = sbase + (size_t)cell * C_;
                    #pragma unroll
                    for (int q = 0; q < C_ / 4; q++) {
                        float v0 = wgt * sctx[p][q*4+0];
                        float v1 = wgt * sctx[p][q*4+1];
                        float v2 = wgt * sctx[p][q*4+2];
                        float v3 = wgt * sctx[p][q*4+3];
                        asm volatile("red.global.add.v4.f32 [%0], {%1, %2, %3, %4};"
                                     :: "l"(ad + q*4), "f"(v0), "f"(v1), "f"(v2), "f"(v3)
                                     : "memory");
                    }
                }
            }
        }
    }
    __syncthreads();

    // ---- phase 3: one red.v4 per (distinct cell, channel quad) ----
    int n = s_n;
    int total = n * (C_ / 4);
    for (int t = tid; t < total; t += 256) {
        int eidx = t / (C_ / 4);
        int q    = t - eidx * (C_ / 4);
        int slot = slist[eidx];
        int cell = skey[slot];
        const float* wp = &swsum[slot * FH_];
        float acc0 = 0.f, acc1 = 0.f, acc2 = 0.f, acc3 = 0.f;
        #pragma unroll
        for (int p = 0; p < FH_; p++) {
            float wv = wp[p];
            acc0 = fmaf(wv, sctx[p][q*4+0], acc0);
            acc1 = fmaf(wv, sctx[p][q*4+1], acc1);
            acc2 = fmaf(wv, sctx[p][q*4+2], acc2);
            acc3 = fmaf(wv, sctx[p][q*4+3], acc3);
        }
        float* addr = sbase + (size_t)cell * C_ + q * 4;
        asm volatile("red.global.add.v4.f32 [%0], {%1, %2, %3, %4};"
                     :: "l"(addr), "f"(acc0), "f"(acc1), "f"(acc2), "f"(acc3)
                     : "memory");
    }
}

// ---------------------------------------------------------------------------
// transpose: [B][Y*X][C] scratch -> [B][C][Y*X] output (writes ALL elements)
// ---------------------------------------------------------------------------
__global__ __launch_bounds__(128) void transpose_kernel(float* __restrict__ out) {
    __shared__ float tile[32][C_ + 1];
    int b   = blockIdx.y;
    int yx0 = blockIdx.x * 32;
    const float4* s4 = (const float4*)(g_scratch + ((size_t)b * CELLS_ + yx0) * C_);
    for (int p = threadIdx.x; p < 32 * (C_ / 4); p += 128) {
        int cell = p / (C_ / 4);
        int q    = p - cell * (C_ / 4);
        float4 v = s4[cell * (C_ / 4) + q];
        tile[cell][q*4+0] = v.x; tile[cell][q*4+1] = v.y;
        tile[cell][q*4+2] = v.z; tile[cell][q*4+3] = v.w;
    }
    __syncthreads();
    float* ob = out + (size_t)b * C_ * CELLS_ + yx0;
    for (int p = threadIdx.x; p < C_ * 8; p += 128) {
        int c  = p / 8;
        int i4 = (p - c * 8) * 4;
        float4 v = make_float4(tile[i4+0][c], tile[i4+1][c], tile[i4+2][c], tile[i4+3][c]);
        *(float4*)(ob + (size_t)c * CELLS_ + i4) = v;
    }
}

// ---------------------------------------------------------------------------
extern "C" void kernel_launch(void* const* d_in, const int* in_sizes, int n_in,
                              void* d_out, int out_size) {
    const float* ctx    = (const float*)d_in[0];
    const float* dl     = (const float*)d_in[1];
    const float* s2e    = (const float*)d_in[2];
    const float* intrin = (const float*)d_in[3];
    const float* ida    = (const float*)d_in[4];
    const float* bda    = (const float*)d_in[5];
    float* out = (float*)d_out;

    zero_scratch_kernel<<<OUTN_ / 4 / 256, 256>>>();
    prep_kernel<<<1, 384>>>(s2e, intrin, ida, bda);
    lss_main<<<BN_ * FW_, 256>>>(ctx, dl);
    transpose_kernel<<<dim3(CELLS_ / 32, B_), 128>>>(out);
}